// round 12
// baseline (speedup 1.0000x reference)
#include <cuda_runtime.h>
#include <cstdint>

#define NN      50000
#define NE      800000
#define MROWS   100000      // B*N rows
#define EPS_BN  1e-5f
#define SCAN_NB 196         // ceil(NN/256)

// ---------------- scratch (device globals; no allocation allowed) ----------------
__device__ float g_buf1[(size_t)MROWS * 64];   // GEMM outputs (pre-aggregation), node-interleaved
__device__ float g_buf2[(size_t)MROWS * 64];   // post-agg ReLU features
__device__ float g_deg[NN];
__device__ float g_dinv[NN];
__device__ int   g_cnt[NN];
__device__ int   g_cur[NN];
__device__ int   g_rowptr[NN + 1];
__device__ int   g_csr_src[NE];
__device__ float g_csr_norm[NE];
__device__ float g_ew[NE];                     // exp(edge_weight), computed once
__device__ float g_bn[4 * 64];                 // [sum1 | sq1 | sum2 | sq2]
__device__ float g_W2p[64 * 64];               // diag(s1) @ W2
__device__ float g_c2[64];                     // t1 @ W2
__device__ float g_wcp[64];                    // s2 .* Wc
__device__ float g_cc[1];                      // t2 @ Wc + bc
__device__ int   g_is64;                       // edge_index dtype flag
__device__ int   g_bsum[256];                  // scan partials
__device__ int   g_boff[256];                  // scan block offsets

__device__ __forceinline__ int edge_at(const void* ei, long long idx) {
    if (g_is64) return (int)((const long long*)ei)[idx];
    return ((const int*)ei)[idx];
}

// ---------------- init (+ dtype detect folded in) ----------------
__global__ void k_init(const int* __restrict__ p) {
    int i = blockIdx.x * blockDim.x + threadIdx.x;
    if (i < NN) { g_cnt[i] = 0; g_deg[i] = 1.0f; }   // self-loop weight 1
    if (i < 256) g_bn[i] = 0.f;
    if (i == 0) {
        int ornz = 0;
        #pragma unroll
        for (int q = 1; q < 32; q += 2) ornz |= p[q];
        g_is64 = (ornz == 0) ? 1 : 0;
    }
}

// ---------------- degree + per-dest edge count + exp(ew) ----------------
__global__ void k_deg(const void* __restrict__ ei, const float* __restrict__ ew) {
    int e = blockIdx.x * blockDim.x + threadIdx.x;
    if (e >= NE) return;
    int c = edge_at(ei, (long long)NE + e);
    float w = expf(ew[e]);
    g_ew[e] = w;
    atomicAdd(&g_deg[c], w);
    atomicAdd(&g_cnt[c], 1);
}

// ---------------- decoupled 3-phase scan ----------------
__device__ __forceinline__ int block_incl_scan(int v, int tid) {
    __shared__ int ws[8];
    int lane = tid & 31, wid = tid >> 5;
    int x = v;
    #pragma unroll
    for (int off = 1; off < 32; off <<= 1) {
        int y = __shfl_up_sync(0xffffffffu, x, off);
        if (lane >= off) x += y;
    }
    if (lane == 31) ws[wid] = x;
    __syncthreads();
    if (wid == 0) {
        int wv = (lane < 8) ? ws[lane] : 0;
        int wx = wv;
        #pragma unroll
        for (int off = 1; off < 8; off <<= 1) {
            int y = __shfl_up_sync(0xffffffffu, wx, off);
            if (lane >= off) wx += y;
        }
        if (lane < 8) ws[lane] = wx - wv;     // exclusive warp prefix
    }
    __syncthreads();
    return x + ws[wid];
}

__global__ void k_scanA() {        // per-block reduce of g_cnt
    __shared__ int ws[8];
    int tid = threadIdx.x, lane = tid & 31, wid = tid >> 5;
    int i = blockIdx.x * 256 + tid;
    int v = (i < NN) ? g_cnt[i] : 0;
    #pragma unroll
    for (int off = 16; off; off >>= 1) v += __shfl_xor_sync(0xffffffffu, v, off);
    if (lane == 0) ws[wid] = v;
    __syncthreads();
    if (tid == 0) {
        int s = 0;
        #pragma unroll
        for (int w = 0; w < 8; w++) s += ws[w];
        g_bsum[blockIdx.x] = s;
    }
}

__global__ void k_scanB() {        // exclusive scan of 196 block sums
    int tid = threadIdx.x;
    int v = (tid < SCAN_NB) ? g_bsum[tid] : 0;
    int incl = block_incl_scan(v, tid);
    g_boff[tid] = incl - v;
}

__global__ void k_scanC() {        // local scan + apply
    int tid = threadIdx.x;
    int i = blockIdx.x * 256 + tid;
    int v = (i < NN) ? g_cnt[i] : 0;
    int incl = block_incl_scan(v, tid);
    int base = g_boff[blockIdx.x];
    if (i < NN) {
        g_rowptr[i + 1] = base + incl;
        g_cur[i]        = base + incl - v;
        g_dinv[i]       = rsqrtf(g_deg[i]);
    }
    if (i == 0) g_rowptr[0] = 0;
}

// ---------------- fill CSR (by destination) ----------------
__global__ void k_fill(const void* __restrict__ ei) {
    int e = blockIdx.x * blockDim.x + threadIdx.x;
    if (e >= NE) return;
    int r = edge_at(ei, e);
    int c = edge_at(ei, (long long)NE + e);
    float w = g_ew[e];
    int pos = atomicAdd(&g_cur[c], 1);
    g_csr_src[pos]  = r;
    g_csr_norm[pos] = g_dinv[r] * w * g_dinv[c];
}

// ---------------- SGEMM via packed FFMA2 (low register pressure) ----------------
// C[MROWS][64] = A[MROWS][K] * B[K][64]
// 128M x 64N block tile, 256 threads; each thread 4m (2 packed pairs) x 8n
// = 16 f32x2 accumulators (32 regs). A staged [k][m] (pairs pre-packed along m),
// B staged duplicated {b,b}. As row stride 132 floats = 528B keeps 16B alignment.
template <int K, bool FIRST>
__global__ __launch_bounds__(256) void k_gemm(const float* __restrict__ Aarg,
                                              const float* __restrict__ Barg) {
    __shared__ __align__(16) float As[16][132];   // [k][m], m 0..127
    __shared__ __align__(16) float Bsd[16][128];  // duplicated: Bsd[k][2n]=Bsd[k][2n+1]=B[k][n]
    const float* A  = FIRST ? Aarg : (const float*)g_buf2;
    const float* Bm = FIRST ? Barg : (const float*)g_W2p;
    float* C = g_buf1;

    const int tid = threadIdx.x;
    const int bm  = blockIdx.x * 128;
    const int tn  = (tid & 7) * 8;     // n: 0..56
    const int tm  = (tid >> 3) * 4;    // m: 0..124 (4 rows)

    // A loader: 2 threads per row, 8 k's each
    const int arow = tid >> 1;         // 0..127
    const int akh  = (tid & 1) * 8;    // 0 or 8
    const int gr   = bm + arow;
    const bool grok = (gr < MROWS);
    const float* Arow = A + (size_t)(grok ? gr : 0) * K;

    // B loader
    const int bk  = tid >> 4;          // 0..15
    const int bn0 = (tid & 15) * 4;    // 0..60

    unsigned long long acc[2][8];
    #pragma unroll
    for (int p = 0; p < 2; p++)
        #pragma unroll
        for (int j = 0; j < 8; j++) acc[p][j] = 0ULL;

    const float4 z4 = make_float4(0.f, 0.f, 0.f, 0.f);
    float4 st0 = grok ? *(const float4*)(Arow + akh)     : z4;
    float4 st1 = grok ? *(const float4*)(Arow + akh + 4) : z4;

    const int NC = K / 16;
    for (int c = 0; c < NC; c++) {
        // stage A chunk transposed [k][m]
        As[akh + 0][arow] = st0.x; As[akh + 1][arow] = st0.y;
        As[akh + 2][arow] = st0.z; As[akh + 3][arow] = st0.w;
        As[akh + 4][arow] = st1.x; As[akh + 5][arow] = st1.y;
        As[akh + 6][arow] = st1.z; As[akh + 7][arow] = st1.w;
        // stage B chunk duplicated
        {
            float4 b = *(const float4*)(Bm + (size_t)(c * 16 + bk) * 64 + bn0);
            *(float4*)&Bsd[bk][2 * bn0]     = make_float4(b.x, b.x, b.y, b.y);
            *(float4*)&Bsd[bk][2 * bn0 + 4] = make_float4(b.z, b.z, b.w, b.w);
        }
        __syncthreads();
        // prefetch next A chunk
        if (c + 1 < NC) {
            st0 = grok ? *(const float4*)(Arow + (c + 1) * 16 + akh)     : z4;
            st1 = grok ? *(const float4*)(Arow + (c + 1) * 16 + akh + 4) : z4;
        }
        #pragma unroll
        for (int kk = 0; kk < 16; kk++) {
            ulonglong2 pa = *(const ulonglong2*)&As[kk][tm];     // 2 m-pairs
            unsigned long long ap[2] = {pa.x, pa.y};
            ulonglong2 pb0 = *(const ulonglong2*)&Bsd[kk][2 * tn];
            ulonglong2 pb1 = *(const ulonglong2*)&Bsd[kk][2 * tn + 4];
            ulonglong2 pb2 = *(const ulonglong2*)&Bsd[kk][2 * tn + 8];
            ulonglong2 pb3 = *(const ulonglong2*)&Bsd[kk][2 * tn + 12];
            unsigned long long bd[8] = {pb0.x, pb0.y, pb1.x, pb1.y,
                                        pb2.x, pb2.y, pb3.x, pb3.y};
            #pragma unroll
            for (int p = 0; p < 2; p++)
                #pragma unroll
                for (int j = 0; j < 8; j++)
                    asm("fma.rn.f32x2 %0, %1, %2, %3;"
                        : "=l"(acc[p][j])
                        : "l"(ap[p]), "l"(bd[j]), "l"(acc[p][j]));
        }
        __syncthreads();
    }

    // epilogue: pair p holds rows (tm+2p, tm+2p+1) in (lo, hi)
    #pragma unroll
    for (int p = 0; p < 2; p++) {
        #pragma unroll
        for (int half = 0; half < 2; half++) {
            int m = bm + tm + 2 * p + half;
            if (m < MROWS) {
                int dst;
                if (FIRST) { int b = m / NN; int n = m - b * NN; dst = n * 2 + b; }
                else       { dst = m; }
                float v[8];
                #pragma unroll
                for (int j = 0; j < 8; j++) {
                    unsigned long long u = acc[p][j];
                    v[j] = half ? __uint_as_float((unsigned)(u >> 32))
                                : __uint_as_float((unsigned)(u & 0xffffffffu));
                }
                float* cp = C + (size_t)dst * 64 + tn;
                *(float4*)cp       = make_float4(v[0], v[1], v[2], v[3]);
                *(float4*)(cp + 4) = make_float4(v[4], v[5], v[6], v[7]);
            }
        }
    }
}

// ---------------- aggregation: g_buf2[n][:] = relu( A @ g_buf1 + bias (+ rs*c2) ), BN stats ----------------
template <bool L2F>
__global__ __launch_bounds__(256) void k_agg(const float* __restrict__ bias) {
    __shared__ float sred[128];
    const int tid = threadIdx.x;
    const int lane = tid & 31;
    const int gw = (blockIdx.x * blockDim.x + tid) >> 5;
    const int nw = (gridDim.x * blockDim.x) >> 5;
    const int j0 = lane * 4;
    const int ch = j0 & 63;
    const float* __restrict__ hin = g_buf1;
    float* __restrict__ hout = g_buf2;

    for (int i = tid; i < 128; i += blockDim.x) sred[i] = 0.f;
    __syncthreads();

    float4 bv = *(const float4*)(bias + ch);
    float4 c2v = make_float4(0.f, 0.f, 0.f, 0.f);
    if (L2F) c2v = *(const float4*)(g_c2 + ch);

    float4 ps = make_float4(0.f, 0.f, 0.f, 0.f);
    float4 pq = make_float4(0.f, 0.f, 0.f, 0.f);

    for (int n = gw; n < NN; n += nw) {
        int beg = g_rowptr[n], end = g_rowptr[n + 1];
        float4 a0 = make_float4(0.f, 0.f, 0.f, 0.f);
        float4 a1 = make_float4(0.f, 0.f, 0.f, 0.f);
        float4 a2 = make_float4(0.f, 0.f, 0.f, 0.f);
        float4 a3 = make_float4(0.f, 0.f, 0.f, 0.f);
        float rsl = 0.f;
        for (int eb = beg; eb < end; eb += 32) {
            int rem = end - eb;
            int cnt = rem < 32 ? rem : 32;
            int sl = n; float wl = 0.f;
            if (lane < cnt) { sl = g_csr_src[eb + lane]; wl = g_csr_norm[eb + lane]; }
            rsl += wl;
            int cnt4 = (cnt + 3) & ~3;
            for (int i = 0; i < cnt4; i += 4) {
                int   s0 = __shfl_sync(0xffffffffu, sl, i);
                int   s1 = __shfl_sync(0xffffffffu, sl, i + 1);
                int   s2 = __shfl_sync(0xffffffffu, sl, i + 2);
                int   s3 = __shfl_sync(0xffffffffu, sl, i + 3);
                float w0 = __shfl_sync(0xffffffffu, wl, i);
                float w1 = __shfl_sync(0xffffffffu, wl, i + 1);
                float w2 = __shfl_sync(0xffffffffu, wl, i + 2);
                float w3 = __shfl_sync(0xffffffffu, wl, i + 3);
                float4 v0 = __ldg((const float4*)(hin + (size_t)s0 * 128 + j0));
                float4 v1 = __ldg((const float4*)(hin + (size_t)s1 * 128 + j0));
                float4 v2 = __ldg((const float4*)(hin + (size_t)s2 * 128 + j0));
                float4 v3 = __ldg((const float4*)(hin + (size_t)s3 * 128 + j0));
                a0.x = fmaf(w0, v0.x, a0.x); a0.y = fmaf(w0, v0.y, a0.y);
                a0.z = fmaf(w0, v0.z, a0.z); a0.w = fmaf(w0, v0.w, a0.w);
                a1.x = fmaf(w1, v1.x, a1.x); a1.y = fmaf(w1, v1.y, a1.y);
                a1.z = fmaf(w1, v1.z, a1.z); a1.w = fmaf(w1, v1.w, a1.w);
                a2.x = fmaf(w2, v2.x, a2.x); a2.y = fmaf(w2, v2.y, a2.y);
                a2.z = fmaf(w2, v2.z, a2.z); a2.w = fmaf(w2, v2.w, a2.w);
                a3.x = fmaf(w3, v3.x, a3.x); a3.y = fmaf(w3, v3.y, a3.y);
                a3.z = fmaf(w3, v3.z, a3.z); a3.w = fmaf(w3, v3.w, a3.w);
            }
        }
        float rs = rsl;
        #pragma unroll
        for (int off = 16; off; off >>= 1) rs += __shfl_xor_sync(0xffffffffu, rs, off);
        float di = g_dinv[n];
        float ws = di * di;
        rs += ws;
        float4 v = *(const float4*)(hin + (size_t)n * 128 + j0);
        float4 r;
        r.x = (a0.x + a1.x) + (a2.x + a3.x) + ws * v.x + bv.x;
        r.y = (a0.y + a1.y) + (a2.y + a3.y) + ws * v.y + bv.y;
        r.z = (a0.z + a1.z) + (a2.z + a3.z) + ws * v.z + bv.z;
        r.w = (a0.w + a1.w) + (a2.w + a3.w) + ws * v.w + bv.w;
        if (L2F) {
            r.x = fmaf(rs, c2v.x, r.x); r.y = fmaf(rs, c2v.y, r.y);
            r.z = fmaf(rs, c2v.z, r.z); r.w = fmaf(rs, c2v.w, r.w);
        }
        r.x = fmaxf(r.x, 0.f); r.y = fmaxf(r.y, 0.f);
        r.z = fmaxf(r.z, 0.f); r.w = fmaxf(r.w, 0.f);
        *(float4*)(hout + (size_t)n * 128 + j0) = r;
        ps.x += r.x; ps.y += r.y; ps.z += r.z; ps.w += r.w;
        pq.x = fmaf(r.x, r.x, pq.x); pq.y = fmaf(r.y, r.y, pq.y);
        pq.z = fmaf(r.z, r.z, pq.z); pq.w = fmaf(r.w, r.w, pq.w);
    }
    atomicAdd(&sred[ch + 0], ps.x); atomicAdd(&sred[ch + 1], ps.y);
    atomicAdd(&sred[ch + 2], ps.z); atomicAdd(&sred[ch + 3], ps.w);
    atomicAdd(&sred[64 + ch + 0], pq.x); atomicAdd(&sred[64 + ch + 1], pq.y);
    atomicAdd(&sred[64 + ch + 2], pq.z); atomicAdd(&sred[64 + ch + 3], pq.w);
    __syncthreads();
    if (tid < 128) {
        float val = sred[tid];
        if (val != 0.f) atomicAdd(&g_bn[(L2F ? 128 : 0) + tid], val);
    }
}

// ---------------- fold BN1 into W2 ----------------
__global__ void k_bnfold1(const float* __restrict__ g1, const float* __restrict__ be1,
                          const float* __restrict__ W2) {
    __shared__ float ss[64], st[64];
    int k = threadIdx.x;  // 64 threads
    const float inv = 1.0f / (float)MROWS;
    float m = g_bn[k] * inv;
    float v = g_bn[64 + k] * inv - m * m;
    float s = g1[k] * rsqrtf(v + EPS_BN);
    float t = fmaf(-m, s, be1[k]);
    ss[k] = s; st[k] = t;
    __syncthreads();
    float c = 0.f;
    for (int r = 0; r < 64; r++) {
        float w = W2[r * 64 + k];
        c = fmaf(st[r], w, c);
        g_W2p[r * 64 + k] = ss[r] * w;
    }
    g_c2[k] = c;
}

// ---------------- fold BN2 into classifier ----------------
__global__ void k_bnfold2(const float* __restrict__ g2, const float* __restrict__ be2,
                          const float* __restrict__ Wc, const float* __restrict__ bc) {
    __shared__ float red[64];
    int k = threadIdx.x;  // 64 threads
    const float inv = 1.0f / (float)MROWS;
    float m = g_bn[128 + k] * inv;
    float v = g_bn[192 + k] * inv - m * m;
    float s = g2[k] * rsqrtf(v + EPS_BN);
    float t = fmaf(-m, s, be2[k]);
    float wc = Wc[k];
    g_wcp[k] = s * wc;
    red[k] = t * wc;
    __syncthreads();
    for (int off = 32; off; off >>= 1) {
        if (k < off) red[k] += red[k + off];
        __syncthreads();
    }
    if (k == 0) g_cc[0] = red[0] + bc[0];
}

// ---------------- classifier: out[b*N+n] = h2bn[n,b,:] . wcp + cc ----------------
__global__ __launch_bounds__(256) void k_cls(float* __restrict__ out) {
    const int lane = threadIdx.x & 31;
    const int gw = (blockIdx.x * blockDim.x + threadIdx.x) >> 5;
    const int nw = (gridDim.x * blockDim.x) >> 5;
    const int j0 = lane * 4;
    float4 wv = *(const float4*)(g_wcp + (j0 & 63));
    float cc = g_cc[0];
    for (int n = gw; n < NN; n += nw) {
        float4 v = *(const float4*)(g_buf2 + (size_t)n * 128 + j0);
        float d = v.x * wv.x + v.y * wv.y + v.z * wv.z + v.w * wv.w;
        d += __shfl_down_sync(0xffffffffu, d, 8, 16);
        d += __shfl_down_sync(0xffffffffu, d, 4, 16);
        d += __shfl_down_sync(0xffffffffu, d, 2, 16);
        d += __shfl_down_sync(0xffffffffu, d, 1, 16);
        if (lane == 0)  out[n]      = d + cc;
        if (lane == 16) out[NN + n] = d + cc;
    }
}

// ---------------- launcher ----------------
extern "C" void kernel_launch(void* const* d_in, const int* in_sizes, int n_in,
                              void* d_out, int out_size) {
    (void)in_sizes; (void)n_in; (void)out_size;
    const float* x    = (const float*)d_in[0];
    const float* ew   = (const float*)d_in[1];
    const float* W1   = (const float*)d_in[2];
    const float* b1   = (const float*)d_in[3];
    const float* W2   = (const float*)d_in[4];
    const float* b2   = (const float*)d_in[5];
    const float* g1   = (const float*)d_in[6];
    const float* be1  = (const float*)d_in[7];
    const float* g2   = (const float*)d_in[8];
    const float* be2  = (const float*)d_in[9];
    const float* Wc   = (const float*)d_in[10];
    const float* bc   = (const float*)d_in[11];
    const void*  eidx = d_in[12];
    float* out = (float*)d_out;

    const int EB = (NE + 255) / 256;
    const int GB = (MROWS + 127) / 128;

    k_init<<<196, 256>>>((const int*)eidx);
    k_deg<<<EB, 256>>>(eidx, ew);
    k_scanA<<<SCAN_NB, 256>>>();
    k_scanB<<<1, 256>>>();
    k_scanC<<<SCAN_NB, 256>>>();
    k_fill<<<EB, 256>>>(eidx);

    // layer 1: h = x@W1 (interleaved layout) -> agg+b1+relu+bn1-stats
    k_gemm<128, true><<<GB, 256>>>(x, W1);
    k_agg<false><<<2048, 256>>>(b1);
    k_bnfold1<<<1, 64>>>(g1, be1, W2);

    // layer 2: h = bn1(h1)@W2 (folded) -> agg+b2+rs*c2+relu+bn2-stats
    k_gemm<64, false><<<GB, 256>>>(x, W1);   // args unused for FIRST=false
    k_agg<true><<<2048, 256>>>(b2);
    k_bnfold2<<<1, 64>>>(g2, be2, Wc, bc);

    // classifier
    k_cls<<<1024, 256>>>(out);
}

// round 13
// speedup vs baseline: 1.9856x; 1.9856x over previous
#include <cuda_runtime.h>
#include <cstdint>

#define NN      50000
#define NE      800000
#define MROWS   100000      // B*N rows
#define EPS_BN  1e-5f
#define SCAN_NB 196         // ceil(NN/256)

// ---------------- scratch (device globals; no allocation allowed) ----------------
__device__ float g_buf1[(size_t)MROWS * 64];   // GEMM outputs (pre-aggregation), node-interleaved
__device__ float g_buf2[(size_t)MROWS * 64];   // post-agg ReLU features
__device__ float g_deg[NN];
__device__ float g_dinv[NN];
__device__ int   g_cnt[NN];
__device__ int   g_cur[NN];
__device__ int   g_rowptr[NN + 1];
__device__ int   g_csr_src[NE];
__device__ float g_csr_norm[NE];
__device__ float g_ew[NE];                     // exp(edge_weight), computed once
__device__ float g_bn[4 * 64];                 // [sum1 | sq1 | sum2 | sq2]
__device__ float g_W2p[64 * 64];               // diag(s1) @ W2
__device__ float g_c2[64];                     // t1 @ W2
__device__ float g_wcp[64];                    // s2 .* Wc
__device__ float g_cc[1];                      // t2 @ Wc + bc
__device__ int   g_is64;                       // edge_index dtype flag
__device__ int   g_bsum[256];                  // scan partials
__device__ int   g_boff[256];                  // scan block offsets

__device__ __forceinline__ int edge_at(const void* ei, long long idx) {
    if (g_is64) return (int)((const long long*)ei)[idx];
    return ((const int*)ei)[idx];
}

// ---------------- init (+ dtype detect folded in) ----------------
__global__ void k_init(const int* __restrict__ p) {
    int i = blockIdx.x * blockDim.x + threadIdx.x;
    if (i < NN) { g_cnt[i] = 0; g_deg[i] = 1.0f; }   // self-loop weight 1
    if (i < 256) g_bn[i] = 0.f;
    if (i == 0) {
        int ornz = 0;
        #pragma unroll
        for (int q = 1; q < 32; q += 2) ornz |= p[q];
        g_is64 = (ornz == 0) ? 1 : 0;
    }
}

// ---------------- degree + per-dest edge count + exp(ew) ----------------
__global__ void k_deg(const void* __restrict__ ei, const float* __restrict__ ew) {
    int e = blockIdx.x * blockDim.x + threadIdx.x;
    if (e >= NE) return;
    int c = edge_at(ei, (long long)NE + e);
    float w = expf(ew[e]);
    g_ew[e] = w;
    atomicAdd(&g_deg[c], w);
    atomicAdd(&g_cnt[c], 1);
}

// ---------------- decoupled 3-phase scan ----------------
__device__ __forceinline__ int block_incl_scan(int v, int tid) {
    __shared__ int ws[8];
    int lane = tid & 31, wid = tid >> 5;
    int x = v;
    #pragma unroll
    for (int off = 1; off < 32; off <<= 1) {
        int y = __shfl_up_sync(0xffffffffu, x, off);
        if (lane >= off) x += y;
    }
    if (lane == 31) ws[wid] = x;
    __syncthreads();
    if (wid == 0) {
        int wv = (lane < 8) ? ws[lane] : 0;
        int wx = wv;
        #pragma unroll
        for (int off = 1; off < 8; off <<= 1) {
            int y = __shfl_up_sync(0xffffffffu, wx, off);
            if (lane >= off) wx += y;
        }
        if (lane < 8) ws[lane] = wx - wv;     // exclusive warp prefix
    }
    __syncthreads();
    return x + ws[wid];
}

__global__ void k_scanA() {        // per-block reduce of g_cnt
    __shared__ int ws[8];
    int tid = threadIdx.x, lane = tid & 31, wid = tid >> 5;
    int i = blockIdx.x * 256 + tid;
    int v = (i < NN) ? g_cnt[i] : 0;
    #pragma unroll
    for (int off = 16; off; off >>= 1) v += __shfl_xor_sync(0xffffffffu, v, off);
    if (lane == 0) ws[wid] = v;
    __syncthreads();
    if (tid == 0) {
        int s = 0;
        #pragma unroll
        for (int w = 0; w < 8; w++) s += ws[w];
        g_bsum[blockIdx.x] = s;
    }
}

__global__ void k_scanB() {        // exclusive scan of 196 block sums
    int tid = threadIdx.x;
    int v = (tid < SCAN_NB) ? g_bsum[tid] : 0;
    int incl = block_incl_scan(v, tid);
    g_boff[tid] = incl - v;
}

__global__ void k_scanC() {        // local scan + apply
    int tid = threadIdx.x;
    int i = blockIdx.x * 256 + tid;
    int v = (i < NN) ? g_cnt[i] : 0;
    int incl = block_incl_scan(v, tid);
    int base = g_boff[blockIdx.x];
    if (i < NN) {
        g_rowptr[i + 1] = base + incl;
        g_cur[i]        = base + incl - v;
        g_dinv[i]       = rsqrtf(g_deg[i]);
    }
    if (i == 0) g_rowptr[0] = 0;
}

// ---------------- fill CSR (by destination) ----------------
__global__ void k_fill(const void* __restrict__ ei) {
    int e = blockIdx.x * blockDim.x + threadIdx.x;
    if (e >= NE) return;
    int r = edge_at(ei, e);
    int c = edge_at(ei, (long long)NE + e);
    float w = g_ew[e];
    int pos = atomicAdd(&g_cur[c], 1);
    g_csr_src[pos]  = r;
    g_csr_norm[pos] = g_dinv[r] * w * g_dinv[c];
}

// ---------------- tf32 helpers ----------------
__device__ __forceinline__ void cvt_hilo(float x, unsigned& hi, unsigned& lo) {
    asm("cvt.rna.tf32.f32 %0, %1;" : "=r"(hi) : "f"(x));
    float r = x - __uint_as_float(hi);
    asm("cvt.rna.tf32.f32 %0, %1;" : "=r"(lo) : "f"(r));
}

__device__ __forceinline__ void mma_tf32(float* d, const unsigned* a,
                                         unsigned b0, unsigned b1) {
    asm("mma.sync.aligned.m16n8k8.row.col.f32.tf32.tf32.f32 "
        "{%0,%1,%2,%3}, {%4,%5,%6,%7}, {%8,%9}, {%0,%1,%2,%3};"
        : "+f"(d[0]), "+f"(d[1]), "+f"(d[2]), "+f"(d[3])
        : "r"(a[0]), "r"(a[1]), "r"(a[2]), "r"(a[3]), "r"(b0), "r"(b1));
}

// ---------------- GEMM via 3xTF32 warp MMA ----------------
// C[MROWS][64] = A[MROWS][K] * B[K][64], fp32-accurate via hi/lo tf32 split.
// Block: 128m x 64n, 256 thr (8 warps); warp w -> rows [16w,16w+16), all 64 n.
// Fragments per m16n8k8: A row-major (a0:[g][t] a1:[g+8][t] a2:[g][t+4] a3:[g+8][t+4]),
// B col-major (b0:[t][g] b1:[t+4][g]), D (d0,d1:[g][2t,2t+1] d2,d3:[g+8][...]).
template <int K, bool FIRST>
__global__ __launch_bounds__(256) void k_gemm(const float* __restrict__ Aarg,
                                              const float* __restrict__ Barg) {
    __shared__ unsigned As_hi[128][20], As_lo[128][20];  // [m][k-in-chunk], stride 20 => conflict-free frags
    __shared__ unsigned Bs_hi[64][20],  Bs_lo[64][20];   // [n][k-in-chunk]
    const float* A  = FIRST ? Aarg : (const float*)g_buf2;
    const float* Bm = FIRST ? Barg : (const float*)g_W2p;
    float* C = g_buf1;

    const int tid = threadIdx.x;
    const int warp = tid >> 5, lane = tid & 31;
    const int gid = lane >> 2, tig = lane & 3;   // groupID, thread-in-group
    const int bm = blockIdx.x * 128;

    // A loader: 2 threads per row, 8 k's each
    const int arow = tid >> 1;
    const int akh  = (tid & 1) * 8;
    const int gr   = bm + arow;
    const bool grok = (gr < MROWS);
    const float* Arow_p = A + (size_t)(grok ? gr : 0) * K;

    // B loader: 16 k rows x 4 n each
    const int bk  = tid >> 4;
    const int bn0 = (tid & 15) * 4;

    float d[8][4];
    #pragma unroll
    for (int j = 0; j < 8; j++)
        #pragma unroll
        for (int q = 0; q < 4; q++) d[j][q] = 0.f;

    const float4 z4 = make_float4(0.f, 0.f, 0.f, 0.f);
    float4 pa0 = grok ? *(const float4*)(Arow_p + akh)     : z4;
    float4 pa1 = grok ? *(const float4*)(Arow_p + akh + 4) : z4;
    float4 pb  = *(const float4*)(Bm + (size_t)bk * 64 + bn0);

    const int NC = K / 16;
    for (int c = 0; c < NC; c++) {
        // ---- stage A (hi/lo) ----
        {
            float av[8] = {pa0.x, pa0.y, pa0.z, pa0.w, pa1.x, pa1.y, pa1.z, pa1.w};
            #pragma unroll
            for (int q = 0; q < 8; q++) {
                unsigned hi, lo; cvt_hilo(av[q], hi, lo);
                As_hi[arow][akh + q] = hi;
                As_lo[arow][akh + q] = lo;
            }
        }
        // ---- stage B transposed (hi/lo) ----
        {
            float bv[4] = {pb.x, pb.y, pb.z, pb.w};
            #pragma unroll
            for (int q = 0; q < 4; q++) {
                unsigned hi, lo; cvt_hilo(bv[q], hi, lo);
                Bs_hi[bn0 + q][bk] = hi;
                Bs_lo[bn0 + q][bk] = lo;
            }
        }
        __syncthreads();
        // ---- prefetch next chunk ----
        if (c + 1 < NC) {
            pa0 = grok ? *(const float4*)(Arow_p + (c + 1) * 16 + akh)     : z4;
            pa1 = grok ? *(const float4*)(Arow_p + (c + 1) * 16 + akh + 4) : z4;
            pb  = *(const float4*)(Bm + (size_t)((c + 1) * 16 + bk) * 64 + bn0);
        }
        // ---- compute: two k-steps of 8 ----
        #pragma unroll
        for (int ks = 0; ks < 16; ks += 8) {
            const int r0 = warp * 16 + gid;
            const int kc = ks + tig;
            unsigned ahi[4], alo[4];
            ahi[0] = As_hi[r0][kc];     ahi[1] = As_hi[r0 + 8][kc];
            ahi[2] = As_hi[r0][kc + 4]; ahi[3] = As_hi[r0 + 8][kc + 4];
            alo[0] = As_lo[r0][kc];     alo[1] = As_lo[r0 + 8][kc];
            alo[2] = As_lo[r0][kc + 4]; alo[3] = As_lo[r0 + 8][kc + 4];
            #pragma unroll
            for (int j = 0; j < 8; j++) {
                const int nn = j * 8 + gid;
                unsigned bhi0 = Bs_hi[nn][kc], bhi1 = Bs_hi[nn][kc + 4];
                unsigned blo0 = Bs_lo[nn][kc], blo1 = Bs_lo[nn][kc + 4];
                mma_tf32(d[j], alo, bhi0, bhi1);   // small terms first
                mma_tf32(d[j], ahi, blo0, blo1);
                mma_tf32(d[j], ahi, bhi0, bhi1);
            }
        }
        __syncthreads();
    }

    // ---- epilogue ----
    const int m0 = bm + warp * 16 + gid;
    const int m1 = m0 + 8;
    int dst0 = 0, dst1 = 0;
    if (FIRST) {
        if (m0 < MROWS) { int b = m0 / NN; int n = m0 - b * NN; dst0 = n * 2 + b; }
        if (m1 < MROWS) { int b = m1 / NN; int n = m1 - b * NN; dst1 = n * 2 + b; }
    } else { dst0 = m0; dst1 = m1; }
    #pragma unroll
    for (int j = 0; j < 8; j++) {
        const int n = j * 8 + 2 * tig;
        if (m0 < MROWS) *(float2*)(C + (size_t)dst0 * 64 + n) = make_float2(d[j][0], d[j][1]);
        if (m1 < MROWS) *(float2*)(C + (size_t)dst1 * 64 + n) = make_float2(d[j][2], d[j][3]);
    }
}

// ---------------- aggregation: g_buf2[n][:] = relu( A @ g_buf1 + bias (+ rs*c2) ), BN stats ----------------
template <bool L2F>
__global__ __launch_bounds__(256) void k_agg(const float* __restrict__ bias) {
    __shared__ float sred[128];
    const int tid = threadIdx.x;
    const int lane = tid & 31;
    const int gw = (blockIdx.x * blockDim.x + tid) >> 5;
    const int nw = (gridDim.x * blockDim.x) >> 5;
    const int j0 = lane * 4;
    const int ch = j0 & 63;
    const float* __restrict__ hin = g_buf1;
    float* __restrict__ hout = g_buf2;

    for (int i = tid; i < 128; i += blockDim.x) sred[i] = 0.f;
    __syncthreads();

    float4 bv = *(const float4*)(bias + ch);
    float4 c2v = make_float4(0.f, 0.f, 0.f, 0.f);
    if (L2F) c2v = *(const float4*)(g_c2 + ch);

    float4 ps = make_float4(0.f, 0.f, 0.f, 0.f);
    float4 pq = make_float4(0.f, 0.f, 0.f, 0.f);

    for (int n = gw; n < NN; n += nw) {
        int beg = g_rowptr[n], end = g_rowptr[n + 1];
        float4 a0 = make_float4(0.f, 0.f, 0.f, 0.f);
        float4 a1 = make_float4(0.f, 0.f, 0.f, 0.f);
        float4 a2 = make_float4(0.f, 0.f, 0.f, 0.f);
        float4 a3 = make_float4(0.f, 0.f, 0.f, 0.f);
        float rsl = 0.f;
        for (int eb = beg; eb < end; eb += 32) {
            int rem = end - eb;
            int cnt = rem < 32 ? rem : 32;
            int sl = n; float wl = 0.f;
            if (lane < cnt) { sl = g_csr_src[eb + lane]; wl = g_csr_norm[eb + lane]; }
            rsl += wl;
            int cnt4 = (cnt + 3) & ~3;
            for (int i = 0; i < cnt4; i += 4) {
                int   s0 = __shfl_sync(0xffffffffu, sl, i);
                int   s1 = __shfl_sync(0xffffffffu, sl, i + 1);
                int   s2 = __shfl_sync(0xffffffffu, sl, i + 2);
                int   s3 = __shfl_sync(0xffffffffu, sl, i + 3);
                float w0 = __shfl_sync(0xffffffffu, wl, i);
                float w1 = __shfl_sync(0xffffffffu, wl, i + 1);
                float w2 = __shfl_sync(0xffffffffu, wl, i + 2);
                float w3 = __shfl_sync(0xffffffffu, wl, i + 3);
                float4 v0 = __ldg((const float4*)(hin + (size_t)s0 * 128 + j0));
                float4 v1 = __ldg((const float4*)(hin + (size_t)s1 * 128 + j0));
                float4 v2 = __ldg((const float4*)(hin + (size_t)s2 * 128 + j0));
                float4 v3 = __ldg((const float4*)(hin + (size_t)s3 * 128 + j0));
                a0.x = fmaf(w0, v0.x, a0.x); a0.y = fmaf(w0, v0.y, a0.y);
                a0.z = fmaf(w0, v0.z, a0.z); a0.w = fmaf(w0, v0.w, a0.w);
                a1.x = fmaf(w1, v1.x, a1.x); a1.y = fmaf(w1, v1.y, a1.y);
                a1.z = fmaf(w1, v1.z, a1.z); a1.w = fmaf(w1, v1.w, a1.w);
                a2.x = fmaf(w2, v2.x, a2.x); a2.y = fmaf(w2, v2.y, a2.y);
                a2.z = fmaf(w2, v2.z, a2.z); a2.w = fmaf(w2, v2.w, a2.w);
                a3.x = fmaf(w3, v3.x, a3.x); a3.y = fmaf(w3, v3.y, a3.y);
                a3.z = fmaf(w3, v3.z, a3.z); a3.w = fmaf(w3, v3.w, a3.w);
            }
        }
        float rs = rsl;
        #pragma unroll
        for (int off = 16; off; off >>= 1) rs += __shfl_xor_sync(0xffffffffu, rs, off);
        float di = g_dinv[n];
        float ws = di * di;
        rs += ws;
        float4 v = *(const float4*)(hin + (size_t)n * 128 + j0);
        float4 r;
        r.x = (a0.x + a1.x) + (a2.x + a3.x) + ws * v.x + bv.x;
        r.y = (a0.y + a1.y) + (a2.y + a3.y) + ws * v.y + bv.y;
        r.z = (a0.z + a1.z) + (a2.z + a3.z) + ws * v.z + bv.z;
        r.w = (a0.w + a1.w) + (a2.w + a3.w) + ws * v.w + bv.w;
        if (L2F) {
            r.x = fmaf(rs, c2v.x, r.x); r.y = fmaf(rs, c2v.y, r.y);
            r.z = fmaf(rs, c2v.z, r.z); r.w = fmaf(rs, c2v.w, r.w);
        }
        r.x = fmaxf(r.x, 0.f); r.y = fmaxf(r.y, 0.f);
        r.z = fmaxf(r.z, 0.f); r.w = fmaxf(r.w, 0.f);
        *(float4*)(hout + (size_t)n * 128 + j0) = r;
        ps.x += r.x; ps.y += r.y; ps.z += r.z; ps.w += r.w;
        pq.x = fmaf(r.x, r.x, pq.x); pq.y = fmaf(r.y, r.y, pq.y);
        pq.z = fmaf(r.z, r.z, pq.z); pq.w = fmaf(r.w, r.w, pq.w);
    }
    atomicAdd(&sred[ch + 0], ps.x); atomicAdd(&sred[ch + 1], ps.y);
    atomicAdd(&sred[ch + 2], ps.z); atomicAdd(&sred[ch + 3], ps.w);
    atomicAdd(&sred[64 + ch + 0], pq.x); atomicAdd(&sred[64 + ch + 1], pq.y);
    atomicAdd(&sred[64 + ch + 2], pq.z); atomicAdd(&sred[64 + ch + 3], pq.w);
    __syncthreads();
    if (tid < 128) {
        float val = sred[tid];
        if (val != 0.f) atomicAdd(&g_bn[(L2F ? 128 : 0) + tid], val);
    }
}

// ---------------- fold BN1 into W2 ----------------
__global__ void k_bnfold1(const float* __restrict__ g1, const float* __restrict__ be1,
                          const float* __restrict__ W2) {
    __shared__ float ss[64], st[64];
    int k = threadIdx.x;  // 64 threads
    const float inv = 1.0f / (float)MROWS;
    float m = g_bn[k] * inv;
    float v = g_bn[64 + k] * inv - m * m;
    float s = g1[k] * rsqrtf(v + EPS_BN);
    float t = fmaf(-m, s, be1[k]);
    ss[k] = s; st[k] = t;
    __syncthreads();
    float c = 0.f;
    for (int r = 0; r < 64; r++) {
        float w = W2[r * 64 + k];
        c = fmaf(st[r], w, c);
        g_W2p[r * 64 + k] = ss[r] * w;
    }
    g_c2[k] = c;
}

// ---------------- fold BN2 into classifier ----------------
__global__ void k_bnfold2(const float* __restrict__ g2, const float* __restrict__ be2,
                          const float* __restrict__ Wc, const float* __restrict__ bc) {
    __shared__ float red[64];
    int k = threadIdx.x;  // 64 threads
    const float inv = 1.0f / (float)MROWS;
    float m = g_bn[128 + k] * inv;
    float v = g_bn[192 + k] * inv - m * m;
    float s = g2[k] * rsqrtf(v + EPS_BN);
    float t = fmaf(-m, s, be2[k]);
    float wc = Wc[k];
    g_wcp[k] = s * wc;
    red[k] = t * wc;
    __syncthreads();
    for (int off = 32; off; off >>= 1) {
        if (k < off) red[k] += red[k + off];
        __syncthreads();
    }
    if (k == 0) g_cc[0] = red[0] + bc[0];
}

// ---------------- classifier: out[b*N+n] = h2bn[n,b,:] . wcp + cc ----------------
__global__ __launch_bounds__(256) void k_cls(float* __restrict__ out) {
    const int lane = threadIdx.x & 31;
    const int gw = (blockIdx.x * blockDim.x + threadIdx.x) >> 5;
    const int nw = (gridDim.x * blockDim.x) >> 5;
    const int j0 = lane * 4;
    float4 wv = *(const float4*)(g_wcp + (j0 & 63));
    float cc = g_cc[0];
    for (int n = gw; n < NN; n += nw) {
        float4 v = *(const float4*)(g_buf2 + (size_t)n * 128 + j0);
        float d = v.x * wv.x + v.y * wv.y + v.z * wv.z + v.w * wv.w;
        d += __shfl_down_sync(0xffffffffu, d, 8, 16);
        d += __shfl_down_sync(0xffffffffu, d, 4, 16);
        d += __shfl_down_sync(0xffffffffu, d, 2, 16);
        d += __shfl_down_sync(0xffffffffu, d, 1, 16);
        if (lane == 0)  out[n]      = d + cc;
        if (lane == 16) out[NN + n] = d + cc;
    }
}

// ---------------- launcher ----------------
extern "C" void kernel_launch(void* const* d_in, const int* in_sizes, int n_in,
                              void* d_out, int out_size) {
    (void)in_sizes; (void)n_in; (void)out_size;
    const float* x    = (const float*)d_in[0];
    const float* ew   = (const float*)d_in[1];
    const float* W1   = (const float*)d_in[2];
    const float* b1   = (const float*)d_in[3];
    const float* W2   = (const float*)d_in[4];
    const float* b2   = (const float*)d_in[5];
    const float* g1   = (const float*)d_in[6];
    const float* be1  = (const float*)d_in[7];
    const float* g2   = (const float*)d_in[8];
    const float* be2  = (const float*)d_in[9];
    const float* Wc   = (const float*)d_in[10];
    const float* bc   = (const float*)d_in[11];
    const void*  eidx = d_in[12];
    float* out = (float*)d_out;

    const int EB = (NE + 255) / 256;
    const int GB = (MROWS + 127) / 128;

    k_init<<<196, 256>>>((const int*)eidx);
    k_deg<<<EB, 256>>>(eidx, ew);
    k_scanA<<<SCAN_NB, 256>>>();
    k_scanB<<<1, 256>>>();
    k_scanC<<<SCAN_NB, 256>>>();
    k_fill<<<EB, 256>>>(eidx);

    // layer 1: h = x@W1 (interleaved layout) -> agg+b1+relu+bn1-stats
    k_gemm<128, true><<<GB, 256>>>(x, W1);
    k_agg<false><<<2048, 256>>>(b1);
    k_bnfold1<<<1, 64>>>(g1, be1, W2);

    // layer 2: h = bn1(h1)@W2 (folded) -> agg+b2+rs*c2+relu+bn2-stats
    k_gemm<64, false><<<GB, 256>>>(x, W1);   // args unused for FIRST=false
    k_agg<true><<<2048, 256>>>(b2);
    k_bnfold2<<<1, 64>>>(g2, be2, Wc, bc);

    // classifier
    k_cls<<<1024, 256>>>(out);
}

// round 14
// speedup vs baseline: 2.3097x; 1.1632x over previous
#include <cuda_runtime.h>
#include <cstdint>

#define NN      50000
#define NE      800000
#define MROWS   100000      // B*N rows
#define EPS_BN  1e-5f
#define SCAN_NB 196         // ceil(NN/256)
#define GB      782         // ceil(MROWS/128) gemm tiles
#define GB2     391         // first-half gemm tiles
#define EB      3125        // ceil(NE/256) edge blocks

// ---------------- scratch (device globals; no allocation allowed) ----------------
__device__ float g_buf1[(size_t)MROWS * 64];   // GEMM outputs (pre-aggregation), node-interleaved
__device__ float g_buf2[(size_t)MROWS * 64];   // post-agg ReLU features
__device__ float g_deg[NN];
__device__ float g_dinv[NN];
__device__ int   g_cnt[NN];
__device__ int   g_cur[NN];
__device__ int   g_rowptr[NN + 1];
__device__ int   g_csr_src[NE];
__device__ float g_csr_norm[NE];
__device__ float g_ew[NE];                     // exp(edge_weight), computed once
__device__ float g_bn[4 * 64];                 // [sum1 | sq1 | sum2 | sq2]
__device__ float g_W2p[64 * 64];               // diag(s1) @ W2
__device__ float g_c2[64];                     // t1 @ W2
__device__ int   g_is64;                       // edge_index dtype flag
__device__ int   g_pk[SCAN_NB];                // lookback state: (incl_or_agg<<2)|flag

__device__ __forceinline__ int edge_at(const void* ei, long long idx) {
    if (g_is64) return (int)((const long long*)ei)[idx];
    return ((const int*)ei)[idx];
}

// ---------------- init (+ dtype detect folded in) ----------------
__global__ void k_init(const int* __restrict__ p) {
    int i = blockIdx.x * blockDim.x + threadIdx.x;
    if (i < NN) { g_cnt[i] = 0; g_deg[i] = 1.0f; }   // self-loop weight 1
    if (i < 256) g_bn[i] = 0.f;
    if (i < SCAN_NB) g_pk[i] = 0;
    if (i == 0) {
        int ornz = 0;
        #pragma unroll
        for (int q = 1; q < 32; q += 2) ornz |= p[q];
        g_is64 = (ornz == 0) ? 1 : 0;
    }
}

// ---------------- device pieces for fat kernels ----------------
__device__ __forceinline__ void deg_dev(int chunk, const void* __restrict__ ei,
                                        const float* __restrict__ ew) {
    int e = chunk * 256 + threadIdx.x;
    if (e >= NE) return;
    int c = edge_at(ei, (long long)NE + e);
    float w = expf(ew[e]);
    g_ew[e] = w;
    atomicAdd(&g_deg[c], w);
    atomicAdd(&g_cnt[c], 1);
}

__device__ __forceinline__ void fill_dev(int chunk, const void* __restrict__ ei) {
    int e = chunk * 256 + threadIdx.x;
    if (e >= NE) return;
    int r = edge_at(ei, e);
    int c = edge_at(ei, (long long)NE + e);
    float w = g_ew[e];
    int pos = atomicAdd(&g_cur[c], 1);
    g_csr_src[pos]  = r;
    g_csr_norm[pos] = g_dinv[r] * w * g_dinv[c];
}

// ---------------- scalar SGEMM tile (proven): C[128 rows][64] ----------------
// As row stride 132 floats = 528B keeps LDS.128 16B alignment.
template <int K, bool FIRST>
__device__ __forceinline__ void gemm_dev(int tile, const float* __restrict__ Aarg,
                                         const float* __restrict__ Barg) {
    __shared__ float As[16][132];
    __shared__ float Bs[16][68];
    const float* A  = FIRST ? Aarg : (const float*)g_buf2;
    const float* Bm = FIRST ? Barg : (const float*)g_W2p;
    float* C = g_buf1;

    const int tid  = threadIdx.x;
    const int bm   = tile * 128;
    const int tn   = (tid & 15) * 4;   // 0..60
    const int tm   = (tid >> 4) * 8;   // 0..120
    const int arow = tid >> 1;         // 0..127
    const int akq  = (tid & 1) * 8;    // 0 or 8

    float acc[8][4];
    #pragma unroll
    for (int i = 0; i < 8; i++)
        #pragma unroll
        for (int j = 0; j < 4; j++) acc[i][j] = 0.f;

    const int gr = bm + arow;
    const bool grok = (gr < MROWS);
    const float* Arow = A + (size_t)(grok ? gr : 0) * K;

    for (int k0 = 0; k0 < K; k0 += 16) {
        float4 av0 = make_float4(0.f, 0.f, 0.f, 0.f);
        float4 av1 = make_float4(0.f, 0.f, 0.f, 0.f);
        if (grok) {
            av0 = *(const float4*)(Arow + k0 + akq);
            av1 = *(const float4*)(Arow + k0 + akq + 4);
        }
        As[akq + 0][arow] = av0.x; As[akq + 1][arow] = av0.y;
        As[akq + 2][arow] = av0.z; As[akq + 3][arow] = av0.w;
        As[akq + 4][arow] = av1.x; As[akq + 5][arow] = av1.y;
        As[akq + 6][arow] = av1.z; As[akq + 7][arow] = av1.w;
        {
            int bk = tid >> 4, bj = (tid & 15) * 4;
            *(float4*)&Bs[bk][bj] = *(const float4*)(Bm + (size_t)(k0 + bk) * 64 + bj);
        }
        __syncthreads();
        #pragma unroll
        for (int kk = 0; kk < 16; kk++) {
            float4 a0 = *(const float4*)&As[kk][tm];
            float4 a1 = *(const float4*)&As[kk][tm + 4];
            float4 bb = *(const float4*)&Bs[kk][tn];
            float a[8] = {a0.x, a0.y, a0.z, a0.w, a1.x, a1.y, a1.z, a1.w};
            float b[4] = {bb.x, bb.y, bb.z, bb.w};
            #pragma unroll
            for (int i = 0; i < 8; i++)
                #pragma unroll
                for (int j = 0; j < 4; j++)
                    acc[i][j] = fmaf(a[i], b[j], acc[i][j]);
        }
        __syncthreads();
    }

    #pragma unroll
    for (int i = 0; i < 8; i++) {
        int m = bm + tm + i;
        if (m < MROWS) {
            int dst;
            if (FIRST) { int b = m / NN; int n = m - b * NN; dst = n * 2 + b; }
            else       { dst = m; }
            *(float4*)(C + (size_t)dst * 64 + tn) =
                make_float4(acc[i][0], acc[i][1], acc[i][2], acc[i][3]);
        }
    }
}

// ---------------- fat kernels: overlap gemm1 halves with deg / fill ----------------
__global__ __launch_bounds__(256) void k_fat1(const float* __restrict__ x,
                                              const float* __restrict__ W1,
                                              const void* __restrict__ ei,
                                              const float* __restrict__ ew) {
    if (blockIdx.x < GB2) gemm_dev<128, true>(blockIdx.x, x, W1);
    else                  deg_dev(blockIdx.x - GB2, ei, ew);
}

__global__ __launch_bounds__(256) void k_fat2(const float* __restrict__ x,
                                              const float* __restrict__ W1,
                                              const void* __restrict__ ei) {
    if (blockIdx.x < (GB - GB2)) gemm_dev<128, true>(GB2 + blockIdx.x, x, W1);
    else                         fill_dev(blockIdx.x - (GB - GB2), ei);
}

__global__ __launch_bounds__(256) void k_gemm2() {
    gemm_dev<64, false>(blockIdx.x, nullptr, nullptr);
}

// ---------------- single-pass scan with warp-parallel decoupled lookback ----------------
__device__ __forceinline__ int block_incl_scan(int v, int tid) {
    __shared__ int ws[8];
    int lane = tid & 31, wid = tid >> 5;
    int x = v;
    #pragma unroll
    for (int off = 1; off < 32; off <<= 1) {
        int y = __shfl_up_sync(0xffffffffu, x, off);
        if (lane >= off) x += y;
    }
    if (lane == 31) ws[wid] = x;
    __syncthreads();
    if (wid == 0) {
        int wv = (lane < 8) ? ws[lane] : 0;
        int wx = wv;
        #pragma unroll
        for (int off = 1; off < 8; off <<= 1) {
            int y = __shfl_up_sync(0xffffffffu, wx, off);
            if (lane >= off) wx += y;
        }
        if (lane < 8) ws[lane] = wx - wv;     // exclusive warp prefix
    }
    __syncthreads();
    return x + ws[wid];
}

__global__ __launch_bounds__(256) void k_scan1() {
    const int tid = threadIdx.x, b = blockIdx.x;
    const int lane = tid & 31, wid = tid >> 5;
    int i = b * 256 + tid;
    int v = (i < NN) ? g_cnt[i] : 0;
    int incl = block_incl_scan(v, tid);
    __shared__ int s_base;
    if (wid == 7) {
        int S_b = __shfl_sync(0xffffffffu, incl, 31);   // block total
        if (lane == 31) {
            int flag = (b == 0) ? 2 : 1;                // b0 publishes inclusive at once
            atomicExch(&g_pk[b], (S_b << 2) | flag);
        }
        int run = 0;
        if (b > 0) {
            int base = b - 1;
            while (true) {
                int j = base - lane;
                bool act = (j >= 0);
                int w = act ? atomicAdd(&g_pk[j], 0) : 0;
                while (__any_sync(0xffffffffu, act && (w & 3) == 0)) {
                    if (act && (w & 3) == 0) w = atomicAdd(&g_pk[j], 0);
                }
                int f   = act ? (w & 3) : 0;
                int val = w >> 2;
                unsigned has2 = __ballot_sync(0xffffffffu, act && f == 2);
                int l2 = has2 ? (__ffs(has2) - 1) : 31;
                int part = (act && lane <= l2) ? val : 0;
                #pragma unroll
                for (int off = 16; off; off >>= 1)
                    part += __shfl_xor_sync(0xffffffffu, part, off);
                run += part;
                if (has2) break;
                base -= 32;
            }
            if (lane == 0) atomicExch(&g_pk[b], ((run + S_b) << 2) | 2);
        }
        if (lane == 0) s_base = run;
    }
    __syncthreads();
    int base = s_base;
    if (i < NN) {
        g_rowptr[i + 1] = base + incl;
        g_cur[i]        = base + incl - v;
        g_dinv[i]       = rsqrtf(g_deg[i]);
    }
    if (i == 0) g_rowptr[0] = 0;
}

// ---------------- aggregation: g_buf2[n][:] = relu( A @ g_buf1 + bias (+ rs*c2) ), BN stats ----------------
template <bool L2F>
__global__ __launch_bounds__(256) void k_agg(const float* __restrict__ bias) {
    __shared__ float sred[128];
    const int tid = threadIdx.x;
    const int lane = tid & 31;
    const int gw = (blockIdx.x * blockDim.x + tid) >> 5;
    const int nw = (gridDim.x * blockDim.x) >> 5;
    const int j0 = lane * 4;
    const int ch = j0 & 63;
    const float* __restrict__ hin = g_buf1;
    float* __restrict__ hout = g_buf2;

    for (int i = tid; i < 128; i += blockDim.x) sred[i] = 0.f;
    __syncthreads();

    float4 bv = *(const float4*)(bias + ch);
    float4 c2v = make_float4(0.f, 0.f, 0.f, 0.f);
    if (L2F) c2v = *(const float4*)(g_c2 + ch);

    float4 ps = make_float4(0.f, 0.f, 0.f, 0.f);
    float4 pq = make_float4(0.f, 0.f, 0.f, 0.f);

    for (int n = gw; n < NN; n += nw) {
        int beg = g_rowptr[n], end = g_rowptr[n + 1];
        float4 a0 = make_float4(0.f, 0.f, 0.f, 0.f);
        float4 a1 = make_float4(0.f, 0.f, 0.f, 0.f);
        float4 a2 = make_float4(0.f, 0.f, 0.f, 0.f);
        float4 a3 = make_float4(0.f, 0.f, 0.f, 0.f);
        float rsl = 0.f;
        for (int eb = beg; eb < end; eb += 32) {
            int rem = end - eb;
            int cnt = rem < 32 ? rem : 32;
            int sl = n; float wl = 0.f;
            if (lane < cnt) { sl = g_csr_src[eb + lane]; wl = g_csr_norm[eb + lane]; }
            rsl += wl;
            int cnt4 = (cnt + 3) & ~3;
            for (int i = 0; i < cnt4; i += 4) {
                int   s0 = __shfl_sync(0xffffffffu, sl, i);
                int   s1 = __shfl_sync(0xffffffffu, sl, i + 1);
                int   s2 = __shfl_sync(0xffffffffu, sl, i + 2);
                int   s3 = __shfl_sync(0xffffffffu, sl, i + 3);
                float w0 = __shfl_sync(0xffffffffu, wl, i);
                float w1 = __shfl_sync(0xffffffffu, wl, i + 1);
                float w2 = __shfl_sync(0xffffffffu, wl, i + 2);
                float w3 = __shfl_sync(0xffffffffu, wl, i + 3);
                float4 v0 = __ldg((const float4*)(hin + (size_t)s0 * 128 + j0));
                float4 v1 = __ldg((const float4*)(hin + (size_t)s1 * 128 + j0));
                float4 v2 = __ldg((const float4*)(hin + (size_t)s2 * 128 + j0));
                float4 v3 = __ldg((const float4*)(hin + (size_t)s3 * 128 + j0));
                a0.x = fmaf(w0, v0.x, a0.x); a0.y = fmaf(w0, v0.y, a0.y);
                a0.z = fmaf(w0, v0.z, a0.z); a0.w = fmaf(w0, v0.w, a0.w);
                a1.x = fmaf(w1, v1.x, a1.x); a1.y = fmaf(w1, v1.y, a1.y);
                a1.z = fmaf(w1, v1.z, a1.z); a1.w = fmaf(w1, v1.w, a1.w);
                a2.x = fmaf(w2, v2.x, a2.x); a2.y = fmaf(w2, v2.y, a2.y);
                a2.z = fmaf(w2, v2.z, a2.z); a2.w = fmaf(w2, v2.w, a2.w);
                a3.x = fmaf(w3, v3.x, a3.x); a3.y = fmaf(w3, v3.y, a3.y);
                a3.z = fmaf(w3, v3.z, a3.z); a3.w = fmaf(w3, v3.w, a3.w);
            }
        }
        float rs = rsl;
        #pragma unroll
        for (int off = 16; off; off >>= 1) rs += __shfl_xor_sync(0xffffffffu, rs, off);
        float di = g_dinv[n];
        float ws = di * di;
        rs += ws;
        float4 v = *(const float4*)(hin + (size_t)n * 128 + j0);
        float4 r;
        r.x = (a0.x + a1.x) + (a2.x + a3.x) + ws * v.x + bv.x;
        r.y = (a0.y + a1.y) + (a2.y + a3.y) + ws * v.y + bv.y;
        r.z = (a0.z + a1.z) + (a2.z + a3.z) + ws * v.z + bv.z;
        r.w = (a0.w + a1.w) + (a2.w + a3.w) + ws * v.w + bv.w;
        if (L2F) {
            r.x = fmaf(rs, c2v.x, r.x); r.y = fmaf(rs, c2v.y, r.y);
            r.z = fmaf(rs, c2v.z, r.z); r.w = fmaf(rs, c2v.w, r.w);
        }
        r.x = fmaxf(r.x, 0.f); r.y = fmaxf(r.y, 0.f);
        r.z = fmaxf(r.z, 0.f); r.w = fmaxf(r.w, 0.f);
        *(float4*)(hout + (size_t)n * 128 + j0) = r;
        ps.x += r.x; ps.y += r.y; ps.z += r.z; ps.w += r.w;
        pq.x = fmaf(r.x, r.x, pq.x); pq.y = fmaf(r.y, r.y, pq.y);
        pq.z = fmaf(r.z, r.z, pq.z); pq.w = fmaf(r.w, r.w, pq.w);
    }
    atomicAdd(&sred[ch + 0], ps.x); atomicAdd(&sred[ch + 1], ps.y);
    atomicAdd(&sred[ch + 2], ps.z); atomicAdd(&sred[ch + 3], ps.w);
    atomicAdd(&sred[64 + ch + 0], pq.x); atomicAdd(&sred[64 + ch + 1], pq.y);
    atomicAdd(&sred[64 + ch + 2], pq.z); atomicAdd(&sred[64 + ch + 3], pq.w);
    __syncthreads();
    if (tid < 128) {
        float val = sred[tid];
        if (val != 0.f) atomicAdd(&g_bn[(L2F ? 128 : 0) + tid], val);
    }
}

// ---------------- fold BN1 into W2 ----------------
__global__ void k_bnfold1(const float* __restrict__ g1, const float* __restrict__ be1,
                          const float* __restrict__ W2) {
    __shared__ float ss[64], st[64];
    int k = threadIdx.x;  // 64 threads
    const float inv = 1.0f / (float)MROWS;
    float m = g_bn[k] * inv;
    float v = g_bn[64 + k] * inv - m * m;
    float s = g1[k] * rsqrtf(v + EPS_BN);
    float t = fmaf(-m, s, be1[k]);
    ss[k] = s; st[k] = t;
    __syncthreads();
    float c = 0.f;
    for (int r = 0; r < 64; r++) {
        float w = W2[r * 64 + k];
        c = fmaf(st[r], w, c);
        g_W2p[r * 64 + k] = ss[r] * w;
    }
    g_c2[k] = c;
}

// ---------------- classifier with inline BN2 fold ----------------
__global__ __launch_bounds__(256) void k_cls(const float* __restrict__ g2,
                                             const float* __restrict__ be2,
                                             const float* __restrict__ Wc,
                                             const float* __restrict__ bc,
                                             float* __restrict__ out) {
    __shared__ __align__(16) float swc[64];
    __shared__ float red[64];
    __shared__ float scc_s;
    const int tid = threadIdx.x;
    if (tid < 64) {
        const float inv = 1.0f / (float)MROWS;
        float m = g_bn[128 + tid] * inv;
        float v = g_bn[192 + tid] * inv - m * m;
        float s = g2[tid] * rsqrtf(v + EPS_BN);
        float t = fmaf(-m, s, be2[tid]);
        float wc = Wc[tid];
        swc[tid] = s * wc;
        red[tid] = t * wc;
    }
    __syncthreads();
    if (tid == 0) {
        float c = 0.f;
        for (int k = 0; k < 64; k++) c += red[k];
        scc_s = c + bc[0];
    }
    __syncthreads();

    const int lane = tid & 31;
    const int gw = (blockIdx.x * blockDim.x + tid) >> 5;
    const int nw = (gridDim.x * blockDim.x) >> 5;
    const int j0 = lane * 4;
    float4 wv = *(const float4*)&swc[j0 & 63];
    float cc = scc_s;
    for (int n = gw; n < NN; n += nw) {
        float4 v = *(const float4*)(g_buf2 + (size_t)n * 128 + j0);
        float d = v.x * wv.x + v.y * wv.y + v.z * wv.z + v.w * wv.w;
        d += __shfl_down_sync(0xffffffffu, d, 8, 16);
        d += __shfl_down_sync(0xffffffffu, d, 4, 16);
        d += __shfl_down_sync(0xffffffffu, d, 2, 16);
        d += __shfl_down_sync(0xffffffffu, d, 1, 16);
        if (lane == 0)  out[n]      = d + cc;
        if (lane == 16) out[NN + n] = d + cc;
    }
}

// ---------------- launcher ----------------
extern "C" void kernel_launch(void* const* d_in, const int* in_sizes, int n_in,
                              void* d_out, int out_size) {
    (void)in_sizes; (void)n_in; (void)out_size;
    const float* x    = (const float*)d_in[0];
    const float* ew   = (const float*)d_in[1];
    const float* W1   = (const float*)d_in[2];
    const float* b1   = (const float*)d_in[3];
    const float* W2   = (const float*)d_in[4];
    const float* b2   = (const float*)d_in[5];
    const float* g1   = (const float*)d_in[6];
    const float* be1  = (const float*)d_in[7];
    const float* g2   = (const float*)d_in[8];
    const float* be2  = (const float*)d_in[9];
    const float* Wc   = (const float*)d_in[10];
    const float* bc   = (const float*)d_in[11];
    const void*  eidx = d_in[12];
    float* out = (float*)d_out;

    k_init<<<196, 256>>>((const int*)eidx);
    k_fat1<<<GB2 + EB, 256>>>(x, W1, eidx, ew);           // gemm1 first half ∥ degree
    k_scan1<<<SCAN_NB, 256>>>();                          // single-pass lookback scan
    k_fat2<<<(GB - GB2) + EB, 256>>>(x, W1, eidx);        // gemm1 second half ∥ CSR fill
    k_agg<false><<<2048, 256>>>(b1);
    k_bnfold1<<<1, 64>>>(g1, be1, W2);
    k_gemm2<<<GB, 256>>>();
    k_agg<true><<<2048, 256>>>(b2);
    k_cls<<<1024, 256>>>(g2, be2, Wc, bc, out);           // BN2 fold inlined
}

// round 15
// speedup vs baseline: 2.3250x; 1.0066x over previous
#include <cuda_runtime.h>
#include <cstdint>

#define NN      50000
#define NE      800000
#define MROWS   100000      // B*N rows
#define EPS_BN  1e-5f
#define SCAN_NB 196         // ceil(NN/256)
#define GB      782         // ceil(MROWS/128) gemm tiles
#define GB2     391         // first-half gemm tiles
#define EB      3125        // ceil(NE/256) edge blocks

// ---------------- scratch (device globals; no allocation allowed) ----------------
__device__ float g_buf1[(size_t)MROWS * 64];   // GEMM outputs (pre-aggregation), node-interleaved
__device__ float g_buf2[(size_t)MROWS * 64];   // post-agg ReLU features
__device__ float g_deg[NN];
__device__ float g_dinv[NN];
__device__ int   g_cnt[NN];
__device__ int   g_cur[NN];
__device__ int   g_rowptr[NN + 1];
__device__ int   g_csr_src[NE];
__device__ float g_csr_norm[NE];
__device__ float g_ew[NE];                     // exp(edge_weight), computed once
__device__ float g_bn[4 * 64];                 // [sum1 | sq1 | sum2 | sq2]
__device__ float g_W2p[64 * 64];               // diag(s1) @ W2
__device__ float g_c2[64];                     // t1 @ W2
__device__ int   g_is64;                       // edge_index dtype flag
__device__ int   g_pk[SCAN_NB];                // lookback state: (incl_or_agg<<2)|flag

__device__ __forceinline__ int edge_at(const void* ei, long long idx) {
    if (g_is64) return (int)((const long long*)ei)[idx];
    return ((const int*)ei)[idx];
}

// ---------------- init (+ dtype detect folded in) ----------------
__global__ void k_init(const int* __restrict__ p) {
    int i = blockIdx.x * blockDim.x + threadIdx.x;
    if (i < NN) { g_cnt[i] = 0; g_deg[i] = 1.0f; }   // self-loop weight 1
    if (i < 256) g_bn[i] = 0.f;
    if (i < SCAN_NB) g_pk[i] = 0;
    if (i == 0) {
        int ornz = 0;
        #pragma unroll
        for (int q = 1; q < 32; q += 2) ornz |= p[q];
        g_is64 = (ornz == 0) ? 1 : 0;
    }
}

// ---------------- device pieces for fat kernels ----------------
__device__ __forceinline__ void deg_dev(int chunk, const void* __restrict__ ei,
                                        const float* __restrict__ ew) {
    int e = chunk * 256 + threadIdx.x;
    if (e >= NE) return;
    int c = edge_at(ei, (long long)NE + e);
    float w = expf(ew[e]);
    g_ew[e] = w;
    atomicAdd(&g_deg[c], w);
    atomicAdd(&g_cnt[c], 1);
}

__device__ __forceinline__ void fill_dev(int chunk, const void* __restrict__ ei) {
    int e = chunk * 256 + threadIdx.x;
    if (e >= NE) return;
    int r = edge_at(ei, e);
    int c = edge_at(ei, (long long)NE + e);
    float w = g_ew[e];
    int pos = atomicAdd(&g_cur[c], 1);
    g_csr_src[pos]  = r;
    g_csr_norm[pos] = g_dinv[r] * w * g_dinv[c];
}

// ---------------- scalar SGEMM tile, double-buffered smem: C[128 rows][64] ----------------
// Row strides: As 132 floats = 528B (16B-aligned), Bs 68 floats = 272B (16B-aligned).
// One __syncthreads per k-chunk (ping-pong buffers); LDG prefetch lands under compute.
template <int K, bool FIRST>
__device__ __forceinline__ void gemm_dev(int tile, const float* __restrict__ Aarg,
                                         const float* __restrict__ Barg) {
    __shared__ __align__(16) float As[2][16][132];
    __shared__ __align__(16) float Bs[2][16][68];
    const float* A  = FIRST ? Aarg : (const float*)g_buf2;
    const float* Bm = FIRST ? Barg : (const float*)g_W2p;
    float* C = g_buf1;

    const int tid  = threadIdx.x;
    const int bm   = tile * 128;
    const int tn   = (tid & 15) * 4;   // 0..60
    const int tm   = (tid >> 4) * 8;   // 0..120
    const int arow = tid >> 1;         // 0..127
    const int akq  = (tid & 1) * 8;    // 0 or 8
    const int bk   = tid >> 4;         // 0..15
    const int bj   = (tid & 15) * 4;   // 0..60

    float acc[8][4];
    #pragma unroll
    for (int i = 0; i < 8; i++)
        #pragma unroll
        for (int j = 0; j < 4; j++) acc[i][j] = 0.f;

    const int gr = bm + arow;
    const bool grok = (gr < MROWS);
    const float* Arow = A + (size_t)(grok ? gr : 0) * K;

    const float4 z4 = make_float4(0.f, 0.f, 0.f, 0.f);
    float4 av0 = grok ? *(const float4*)(Arow + akq)     : z4;
    float4 av1 = grok ? *(const float4*)(Arow + akq + 4) : z4;
    float4 bv  = *(const float4*)(Bm + (size_t)bk * 64 + bj);

    // stage chunk 0 into buffer 0
    As[0][akq + 0][arow] = av0.x; As[0][akq + 1][arow] = av0.y;
    As[0][akq + 2][arow] = av0.z; As[0][akq + 3][arow] = av0.w;
    As[0][akq + 4][arow] = av1.x; As[0][akq + 5][arow] = av1.y;
    As[0][akq + 6][arow] = av1.z; As[0][akq + 7][arow] = av1.w;
    *(float4*)&Bs[0][bk][bj] = bv;
    __syncthreads();

    const int NC = K / 16;
    for (int c = 0; c < NC; c++) {
        const int cur = c & 1;
        if (c + 1 < NC) {   // prefetch next chunk (lands under compute)
            av0 = grok ? *(const float4*)(Arow + (c + 1) * 16 + akq)     : z4;
            av1 = grok ? *(const float4*)(Arow + (c + 1) * 16 + akq + 4) : z4;
            bv  = *(const float4*)(Bm + (size_t)((c + 1) * 16 + bk) * 64 + bj);
        }
        #pragma unroll
        for (int kk = 0; kk < 16; kk++) {
            float4 a0 = *(const float4*)&As[cur][kk][tm];
            float4 a1 = *(const float4*)&As[cur][kk][tm + 4];
            float4 bb = *(const float4*)&Bs[cur][kk][tn];
            float a[8] = {a0.x, a0.y, a0.z, a0.w, a1.x, a1.y, a1.z, a1.w};
            float b[4] = {bb.x, bb.y, bb.z, bb.w};
            #pragma unroll
            for (int i = 0; i < 8; i++)
                #pragma unroll
                for (int j = 0; j < 4; j++)
                    acc[i][j] = fmaf(a[i], b[j], acc[i][j]);
        }
        if (c + 1 < NC) {   // stage next chunk into the other buffer
            const int nxt = 1 - cur;
            As[nxt][akq + 0][arow] = av0.x; As[nxt][akq + 1][arow] = av0.y;
            As[nxt][akq + 2][arow] = av0.z; As[nxt][akq + 3][arow] = av0.w;
            As[nxt][akq + 4][arow] = av1.x; As[nxt][akq + 5][arow] = av1.y;
            As[nxt][akq + 6][arow] = av1.z; As[nxt][akq + 7][arow] = av1.w;
            *(float4*)&Bs[nxt][bk][bj] = bv;
            __syncthreads();
        }
    }

    #pragma unroll
    for (int i = 0; i < 8; i++) {
        int m = bm + tm + i;
        if (m < MROWS) {
            int dst;
            if (FIRST) { int b = m / NN; int n = m - b * NN; dst = n * 2 + b; }
            else       { dst = m; }
            *(float4*)(C + (size_t)dst * 64 + tn) =
                make_float4(acc[i][0], acc[i][1], acc[i][2], acc[i][3]);
        }
    }
}

// ---------------- fat kernels: overlap gemm1 halves with deg / fill ----------------
__global__ __launch_bounds__(256) void k_fat1(const float* __restrict__ x,
                                              const float* __restrict__ W1,
                                              const void* __restrict__ ei,
                                              const float* __restrict__ ew) {
    if (blockIdx.x < GB2) gemm_dev<128, true>(blockIdx.x, x, W1);
    else                  deg_dev(blockIdx.x - GB2, ei, ew);
}

__global__ __launch_bounds__(256) void k_fat2(const float* __restrict__ x,
                                              const float* __restrict__ W1,
                                              const void* __restrict__ ei) {
    if (blockIdx.x < (GB - GB2)) gemm_dev<128, true>(GB2 + blockIdx.x, x, W1);
    else                         fill_dev(blockIdx.x - (GB - GB2), ei);
}

__global__ __launch_bounds__(256) void k_gemm2() {
    gemm_dev<64, false>(blockIdx.x, nullptr, nullptr);
}

// ---------------- single-pass scan with warp-parallel decoupled lookback ----------------
__device__ __forceinline__ int block_incl_scan(int v, int tid) {
    __shared__ int ws[8];
    int lane = tid & 31, wid = tid >> 5;
    int x = v;
    #pragma unroll
    for (int off = 1; off < 32; off <<= 1) {
        int y = __shfl_up_sync(0xffffffffu, x, off);
        if (lane >= off) x += y;
    }
    if (lane == 31) ws[wid] = x;
    __syncthreads();
    if (wid == 0) {
        int wv = (lane < 8) ? ws[lane] : 0;
        int wx = wv;
        #pragma unroll
        for (int off = 1; off < 8; off <<= 1) {
            int y = __shfl_up_sync(0xffffffffu, wx, off);
            if (lane >= off) wx += y;
        }
        if (lane < 8) ws[lane] = wx - wv;     // exclusive warp prefix
    }
    __syncthreads();
    return x + ws[wid];
}

__global__ __launch_bounds__(256) void k_scan1() {
    const int tid = threadIdx.x, b = blockIdx.x;
    const int lane = tid & 31, wid = tid >> 5;
    int i = b * 256 + tid;
    int v = (i < NN) ? g_cnt[i] : 0;
    int incl = block_incl_scan(v, tid);
    __shared__ int s_base;
    if (wid == 7) {
        int S_b = __shfl_sync(0xffffffffu, incl, 31);   // block total
        if (lane == 31) {
            int flag = (b == 0) ? 2 : 1;                // b0 publishes inclusive at once
            atomicExch(&g_pk[b], (S_b << 2) | flag);
        }
        int run = 0;
        if (b > 0) {
            int base = b - 1;
            while (true) {
                int j = base - lane;
                bool act = (j >= 0);
                int w = act ? atomicAdd(&g_pk[j], 0) : 0;
                while (__any_sync(0xffffffffu, act && (w & 3) == 0)) {
                    if (act && (w & 3) == 0) w = atomicAdd(&g_pk[j], 0);
                }
                int f   = act ? (w & 3) : 0;
                int val = w >> 2;
                unsigned has2 = __ballot_sync(0xffffffffu, act && f == 2);
                int l2 = has2 ? (__ffs(has2) - 1) : 31;
                int part = (act && lane <= l2) ? val : 0;
                #pragma unroll
                for (int off = 16; off; off >>= 1)
                    part += __shfl_xor_sync(0xffffffffu, part, off);
                run += part;
                if (has2) break;
                base -= 32;
            }
            if (lane == 0) atomicExch(&g_pk[b], ((run + S_b) << 2) | 2);
        }
        if (lane == 0) s_base = run;
    }
    __syncthreads();
    int base = s_base;
    if (i < NN) {
        g_rowptr[i + 1] = base + incl;
        g_cur[i]        = base + incl - v;
        g_dinv[i]       = rsqrtf(g_deg[i]);
    }
    if (i == 0) g_rowptr[0] = 0;
}

// ---------------- aggregation: g_buf2[n][:] = relu( A @ g_buf1 + bias (+ rs*c2) ), BN stats ----------------
template <bool L2F>
__global__ __launch_bounds__(256) void k_agg(const float* __restrict__ bias) {
    __shared__ float sred[128];
    const int tid = threadIdx.x;
    const int lane = tid & 31;
    const int gw = (blockIdx.x * blockDim.x + tid) >> 5;
    const int nw = (gridDim.x * blockDim.x) >> 5;
    const int j0 = lane * 4;
    const int ch = j0 & 63;
    const float* __restrict__ hin = g_buf1;
    float* __restrict__ hout = g_buf2;

    for (int i = tid; i < 128; i += blockDim.x) sred[i] = 0.f;
    __syncthreads();

    float4 bv = *(const float4*)(bias + ch);
    float4 c2v = make_float4(0.f, 0.f, 0.f, 0.f);
    if (L2F) c2v = *(const float4*)(g_c2 + ch);

    float4 ps = make_float4(0.f, 0.f, 0.f, 0.f);
    float4 pq = make_float4(0.f, 0.f, 0.f, 0.f);

    for (int n = gw; n < NN; n += nw) {
        int beg = g_rowptr[n], end = g_rowptr[n + 1];
        float4 a0 = make_float4(0.f, 0.f, 0.f, 0.f);
        float4 a1 = make_float4(0.f, 0.f, 0.f, 0.f);
        float4 a2 = make_float4(0.f, 0.f, 0.f, 0.f);
        float4 a3 = make_float4(0.f, 0.f, 0.f, 0.f);
        float rsl = 0.f;
        for (int eb = beg; eb < end; eb += 32) {
            int rem = end - eb;
            int cnt = rem < 32 ? rem : 32;
            int sl = n; float wl = 0.f;
            if (lane < cnt) { sl = g_csr_src[eb + lane]; wl = g_csr_norm[eb + lane]; }
            rsl += wl;
            int cnt4 = (cnt + 3) & ~3;
            for (int i = 0; i < cnt4; i += 4) {
                int   s0 = __shfl_sync(0xffffffffu, sl, i);
                int   s1 = __shfl_sync(0xffffffffu, sl, i + 1);
                int   s2 = __shfl_sync(0xffffffffu, sl, i + 2);
                int   s3 = __shfl_sync(0xffffffffu, sl, i + 3);
                float w0 = __shfl_sync(0xffffffffu, wl, i);
                float w1 = __shfl_sync(0xffffffffu, wl, i + 1);
                float w2 = __shfl_sync(0xffffffffu, wl, i + 2);
                float w3 = __shfl_sync(0xffffffffu, wl, i + 3);
                float4 v0 = __ldg((const float4*)(hin + (size_t)s0 * 128 + j0));
                float4 v1 = __ldg((const float4*)(hin + (size_t)s1 * 128 + j0));
                float4 v2 = __ldg((const float4*)(hin + (size_t)s2 * 128 + j0));
                float4 v3 = __ldg((const float4*)(hin + (size_t)s3 * 128 + j0));
                a0.x = fmaf(w0, v0.x, a0.x); a0.y = fmaf(w0, v0.y, a0.y);
                a0.z = fmaf(w0, v0.z, a0.z); a0.w = fmaf(w0, v0.w, a0.w);
                a1.x = fmaf(w1, v1.x, a1.x); a1.y = fmaf(w1, v1.y, a1.y);
                a1.z = fmaf(w1, v1.z, a1.z); a1.w = fmaf(w1, v1.w, a1.w);
                a2.x = fmaf(w2, v2.x, a2.x); a2.y = fmaf(w2, v2.y, a2.y);
                a2.z = fmaf(w2, v2.z, a2.z); a2.w = fmaf(w2, v2.w, a2.w);
                a3.x = fmaf(w3, v3.x, a3.x); a3.y = fmaf(w3, v3.y, a3.y);
                a3.z = fmaf(w3, v3.z, a3.z); a3.w = fmaf(w3, v3.w, a3.w);
            }
        }
        float rs = rsl;
        #pragma unroll
        for (int off = 16; off; off >>= 1) rs += __shfl_xor_sync(0xffffffffu, rs, off);
        float di = g_dinv[n];
        float ws = di * di;
        rs += ws;
        float4 v = *(const float4*)(hin + (size_t)n * 128 + j0);
        float4 r;
        r.x = (a0.x + a1.x) + (a2.x + a3.x) + ws * v.x + bv.x;
        r.y = (a0.y + a1.y) + (a2.y + a3.y) + ws * v.y + bv.y;
        r.z = (a0.z + a1.z) + (a2.z + a3.z) + ws * v.z + bv.z;
        r.w = (a0.w + a1.w) + (a2.w + a3.w) + ws * v.w + bv.w;
        if (L2F) {
            r.x = fmaf(rs, c2v.x, r.x); r.y = fmaf(rs, c2v.y, r.y);
            r.z = fmaf(rs, c2v.z, r.z); r.w = fmaf(rs, c2v.w, r.w);
        }
        r.x = fmaxf(r.x, 0.f); r.y = fmaxf(r.y, 0.f);
        r.z = fmaxf(r.z, 0.f); r.w = fmaxf(r.w, 0.f);
        *(float4*)(hout + (size_t)n * 128 + j0) = r;
        ps.x += r.x; ps.y += r.y; ps.z += r.z; ps.w += r.w;
        pq.x = fmaf(r.x, r.x, pq.x); pq.y = fmaf(r.y, r.y, pq.y);
        pq.z = fmaf(r.z, r.z, pq.z); pq.w = fmaf(r.w, r.w, pq.w);
    }
    atomicAdd(&sred[ch + 0], ps.x); atomicAdd(&sred[ch + 1], ps.y);
    atomicAdd(&sred[ch + 2], ps.z); atomicAdd(&sred[ch + 3], ps.w);
    atomicAdd(&sred[64 + ch + 0], pq.x); atomicAdd(&sred[64 + ch + 1], pq.y);
    atomicAdd(&sred[64 + ch + 2], pq.z); atomicAdd(&sred[64 + ch + 3], pq.w);
    __syncthreads();
    if (tid < 128) {
        float val = sred[tid];
        if (val != 0.f) atomicAdd(&g_bn[(L2F ? 128 : 0) + tid], val);
    }
}

// ---------------- fold BN1 into W2 ----------------
__global__ void k_bnfold1(const float* __restrict__ g1, const float* __restrict__ be1,
                          const float* __restrict__ W2) {
    __shared__ float ss[64], st[64];
    int k = threadIdx.x;  // 64 threads
    const float inv = 1.0f / (float)MROWS;
    float m = g_bn[k] * inv;
    float v = g_bn[64 + k] * inv - m * m;
    float s = g1[k] * rsqrtf(v + EPS_BN);
    float t = fmaf(-m, s, be1[k]);
    ss[k] = s; st[k] = t;
    __syncthreads();
    float c = 0.f;
    for (int r = 0; r < 64; r++) {
        float w = W2[r * 64 + k];
        c = fmaf(st[r], w, c);
        g_W2p[r * 64 + k] = ss[r] * w;
    }
    g_c2[k] = c;
}

// ---------------- classifier with inline BN2 fold ----------------
__global__ __launch_bounds__(256) void k_cls(const float* __restrict__ g2,
                                             const float* __restrict__ be2,
                                             const float* __restrict__ Wc,
                                             const float* __restrict__ bc,
                                             float* __restrict__ out) {
    __shared__ __align__(16) float swc[64];
    __shared__ float red[64];
    __shared__ float scc_s;
    const int tid = threadIdx.x;
    if (tid < 64) {
        const float inv = 1.0f / (float)MROWS;
        float m = g_bn[128 + tid] * inv;
        float v = g_bn[192 + tid] * inv - m * m;
        float s = g2[tid] * rsqrtf(v + EPS_BN);
        float t = fmaf(-m, s, be2[tid]);
        float wc = Wc[tid];
        swc[tid] = s * wc;
        red[tid] = t * wc;
    }
    __syncthreads();
    if (tid == 0) {
        float c = 0.f;
        for (int k = 0; k < 64; k++) c += red[k];
        scc_s = c + bc[0];
    }
    __syncthreads();

    const int lane = tid & 31;
    const int gw = (blockIdx.x * blockDim.x + tid) >> 5;
    const int nw = (gridDim.x * blockDim.x) >> 5;
    const int j0 = lane * 4;
    float4 wv = *(const float4*)&swc[j0 & 63];
    float cc = scc_s;
    for (int n = gw; n < NN; n += nw) {
        float4 v = *(const float4*)(g_buf2 + (size_t)n * 128 + j0);
        float d = v.x * wv.x + v.y * wv.y + v.z * wv.z + v.w * wv.w;
        d += __shfl_down_sync(0xffffffffu, d, 8, 16);
        d += __shfl_down_sync(0xffffffffu, d, 4, 16);
        d += __shfl_down_sync(0xffffffffu, d, 2, 16);
        d += __shfl_down_sync(0xffffffffu, d, 1, 16);
        if (lane == 0)  out[n]      = d + cc;
        if (lane == 16) out[NN + n] = d + cc;
    }
}

// ---------------- launcher ----------------
extern "C" void kernel_launch(void* const* d_in, const int* in_sizes, int n_in,
                              void* d_out, int out_size) {
    (void)in_sizes; (void)n_in; (void)out_size;
    const float* x    = (const float*)d_in[0];
    const float* ew   = (const float*)d_in[1];
    const float* W1   = (const float*)d_in[2];
    const float* b1   = (const float*)d_in[3];
    const float* W2   = (const float*)d_in[4];
    const float* b2   = (const float*)d_in[5];
    const float* g1   = (const float*)d_in[6];
    const float* be1  = (const float*)d_in[7];
    const float* g2   = (const float*)d_in[8];
    const float* be2  = (const float*)d_in[9];
    const float* Wc   = (const float*)d_in[10];
    const float* bc   = (const float*)d_in[11];
    const void*  eidx = d_in[12];
    float* out = (float*)d_out;

    k_init<<<196, 256>>>((const int*)eidx);
    k_fat1<<<GB2 + EB, 256>>>(x, W1, eidx, ew);           // gemm1 first half ∥ degree
    k_scan1<<<SCAN_NB, 256>>>();                          // single-pass lookback scan
    k_fat2<<<(GB - GB2) + EB, 256>>>(x, W1, eidx);        // gemm1 second half ∥ CSR fill
    k_agg<false><<<2048, 256>>>(b1);
    k_bnfold1<<<1, 64>>>(g1, be1, W2);
    k_gemm2<<<GB, 256>>>();
    k_agg<true><<<2048, 256>>>(b2);
    k_cls<<<1024, 256>>>(g2, be2, Wc, bc, out);           // BN2 fold inlined
}